// round 4
// baseline (speedup 1.0000x reference)
#include <cuda_runtime.h>

// SoftmaxProbs: mean_b [ sum_c ( -log_softmax(x)[b,c] * l[b,c] ) ]
//             = mean_b [ lse_b * (sum_c l) - sum_c l*x ]
// 2M rows x 18 classes, fp32. HBM-bound: 288 MB streamed.

#define NC 18
#define BLK 256
#define MAX_CHUNKS 32768   // supports B up to 8.38M rows at 256 rows/block

__device__ double g_partials[MAX_CHUNKS];

__global__ __launch_bounds__(BLK)
void ce_rows_kernel(const float* __restrict__ x,
                    const float* __restrict__ lab,
                    int B)
{
    __shared__ float  sx[BLK * NC];   // 18432 B
    __shared__ float  sl[BLK * NC];   // 18432 B
    __shared__ double sred[BLK / 32];

    const long long row0 = (long long)blockIdx.x * BLK;
    long long rem = (long long)B - row0;
    const int rows = rem < BLK ? (int)rem : BLK;
    const int nf  = rows * NC;          // floats in this chunk (per tensor)
    const int nv4 = nf >> 2;            // float4 count (chunk base is 16B aligned:
                                        // 256*18*4 = 18432 B per chunk)

    const float*  xbase = x   + row0 * NC;
    const float*  lbase = lab + row0 * NC;
    const float4* xv = (const float4*)xbase;
    const float4* lv = (const float4*)lbase;
    float4* sxv = (float4*)sx;
    float4* slv = (float4*)sl;

    // Coalesced stage-in: LDG.128 / STS.128
    for (int i = threadIdx.x; i < nv4; i += BLK) {
        sxv[i] = xv[i];
        slv[i] = lv[i];
    }
    for (int i = (nv4 << 2) + threadIdx.x; i < nf; i += BLK) {
        sx[i] = xbase[i];
        sl[i] = lbase[i];
    }
    __syncthreads();

    double contrib = 0.0;
    if ((int)threadIdx.x < rows) {
        // Conflict-free LDS.64 pattern: row stride 72 B
        const float* rx = sx + threadIdx.x * NC;
        float xr[NC];
        #pragma unroll
        for (int c = 0; c < NC; c++) xr[c] = rx[c];

        float m = xr[0];
        #pragma unroll
        for (int c = 1; c < NC; c++) m = fmaxf(m, xr[c]);

        float s = 0.f;
        #pragma unroll
        for (int c = 0; c < NC; c++) s += __expf(xr[c] - m);
        const float lse = m + __logf(s);

        const float* rl = sl + threadIdx.x * NC;
        float suml = 0.f, dot = 0.f;
        #pragma unroll
        for (int c = 0; c < NC; c++) {
            const float lvv = rl[c];
            suml += lvv;
            dot   = fmaf(lvv, xr[c], dot);
        }
        contrib = (double)(lse * suml - dot);
    }

    // Deterministic block reduction in double
    #pragma unroll
    for (int o = 16; o > 0; o >>= 1)
        contrib += __shfl_down_sync(0xffffffffu, contrib, o);

    const int lane = threadIdx.x & 31;
    const int warp = threadIdx.x >> 5;
    if (lane == 0) sred[warp] = contrib;
    __syncthreads();

    if (warp == 0) {
        double v = (lane < BLK / 32) ? sred[lane] : 0.0;
        #pragma unroll
        for (int o = 4; o > 0; o >>= 1)
            v += __shfl_down_sync(0xffffffffu, v, o);
        if (lane == 0) g_partials[blockIdx.x] = v;
    }
}

__global__ __launch_bounds__(1024)
void ce_finalize_kernel(float* out, int nchunks, int B)
{
    __shared__ double sred[32];
    double v = 0.0;
    for (int i = threadIdx.x; i < nchunks; i += blockDim.x)
        v += g_partials[i];

    #pragma unroll
    for (int o = 16; o > 0; o >>= 1)
        v += __shfl_down_sync(0xffffffffu, v, o);

    const int lane = threadIdx.x & 31;
    const int warp = threadIdx.x >> 5;
    if (lane == 0) sred[warp] = v;
    __syncthreads();

    if (warp == 0) {
        double t = (lane < 32) ? sred[lane] : 0.0;
        if (blockDim.x < 1024 && lane >= (int)(blockDim.x >> 5)) t = 0.0;
        #pragma unroll
        for (int o = 16; o > 0; o >>= 1)
            t += __shfl_down_sync(0xffffffffu, t, o);
        if (lane == 0) out[0] = (float)(t / (double)B);
    }
}

extern "C" void kernel_launch(void* const* d_in, const int* in_sizes, int n_in,
                              void* d_out, int out_size)
{
    const float* x   = (const float*)d_in[0];   // output  [B, 18]
    const float* lab = (const float*)d_in[1];   // labels_soft [B, 18]
    const int B = in_sizes[0] / NC;
    const int nchunks = (B + BLK - 1) / BLK;

    ce_rows_kernel<<<nchunks, BLK>>>(x, lab, B);
    ce_finalize_kernel<<<1, 1024>>>((float*)d_out, nchunks, B);
}

// round 5
// speedup vs baseline: 1.3017x; 1.3017x over previous
#include <cuda_runtime.h>

// SoftmaxProbs: mean_b [ lse_b * (sum_c l) - sum_c l*x ],  2M rows x 18 classes fp32.
// HBM-bound: 288 MB streamed. Persistent grid + cp.async double-buffered smem
// staging + fused last-block finalize (no second kernel).

#define NC 18
#define BLK 128
#define CHUNK_FLOATS (BLK * NC)      // 2304 floats = 9216 B per tensor per stage
#define MAX_GRID 1024

__device__ double       g_partials[MAX_GRID];
__device__ unsigned int g_count = 0;

__device__ __forceinline__ void cpa16(unsigned int saddr, const float4* g) {
    asm volatile("cp.async.cg.shared.global [%0], [%1], 16;" :: "r"(saddr), "l"(g));
}
__device__ __forceinline__ void cpa_commit() {
    asm volatile("cp.async.commit_group;");
}

__global__ __launch_bounds__(BLK)
void ce_main_kernel(const float* __restrict__ x,
                    const float* __restrict__ lab,
                    float* __restrict__ out,
                    int B, int nchunks)
{
    __shared__ float  sx[2][CHUNK_FLOATS];   // 18432 B
    __shared__ float  sl[2][CHUNK_FLOATS];   // 18432 B
    __shared__ double sred[BLK / 32];
    __shared__ int    s_last;

    const int tid = threadIdx.x;

    auto stage = [&](int c, int s) {
        const long long row0 = (long long)c * BLK;
        long long rem = (long long)B - row0;
        const int rows = rem < BLK ? (int)rem : BLK;
        const int nf   = rows * NC;
        const int nv4  = nf >> 2;
        const float* xb = x   + row0 * NC;
        const float* lb = lab + row0 * NC;
        const float4* xb4 = (const float4*)xb;
        const float4* lb4 = (const float4*)lb;
        const unsigned int sxa = (unsigned int)__cvta_generic_to_shared(&sx[s][0]);
        const unsigned int sla = (unsigned int)__cvta_generic_to_shared(&sl[s][0]);
        for (int i = tid; i < nv4; i += BLK) {
            cpa16(sxa + i * 16, xb4 + i);
            cpa16(sla + i * 16, lb4 + i);
        }
        // scalar tail (only possible on the final partial chunk)
        for (int i = (nv4 << 2) + tid; i < nf; i += BLK) {
            sx[s][i] = xb[i];
            sl[s][i] = lb[i];
        }
    };

    const int c0 = blockIdx.x;
    double acc = 0.0;

    if (c0 < nchunks) stage(c0, 0);
    cpa_commit();                       // group for chunk c0 (possibly empty)

    int stg = 0;
    for (int c = c0; c < nchunks; c += gridDim.x, stg ^= 1) {
        const int nxt = c + gridDim.x;
        if (nxt < nchunks) stage(nxt, stg ^ 1);
        cpa_commit();                   // group for nxt (possibly empty)
        asm volatile("cp.async.wait_group 1;");  // chunk c resident
        __syncthreads();

        const long long row0 = (long long)c * BLK;
        long long rem = (long long)B - row0;
        const int rows = rem < BLK ? (int)rem : BLK;

        if (tid < rows) {
            const float* rx = &sx[stg][tid * NC];   // 72B stride: conflict-free LDS.64
            float xr[NC];
            #pragma unroll
            for (int k = 0; k < NC; k++) xr[k] = rx[k];

            float m = xr[0];
            #pragma unroll
            for (int k = 1; k < NC; k++) m = fmaxf(m, xr[k]);

            float s = 0.f;
            #pragma unroll
            for (int k = 0; k < NC; k++) s += __expf(xr[k] - m);
            const float lse = m + __logf(s);

            const float* rl = &sl[stg][tid * NC];
            float suml = 0.f, dot = 0.f;
            #pragma unroll
            for (int k = 0; k < NC; k++) {
                const float lv = rl[k];
                suml += lv;
                dot   = fmaf(lv, xr[k], dot);
            }
            acc += (double)(lse * suml - dot);
        }
        __syncthreads();                // buffer 'stg' reusable next+1 iteration
    }
    asm volatile("cp.async.wait_group 0;");

    // ── per-block deterministic reduction ──
    #pragma unroll
    for (int o = 16; o > 0; o >>= 1)
        acc += __shfl_down_sync(0xffffffffu, acc, o);

    const int lane = tid & 31;
    const int warp = tid >> 5;
    if (lane == 0) sred[warp] = acc;
    __syncthreads();

    if (tid == 0) {
        double v = sred[0] + sred[1] + sred[2] + sred[3];
        g_partials[blockIdx.x] = v;
        __threadfence();
        unsigned prev = atomicAdd(&g_count, 1u);
        s_last = (prev == gridDim.x - 1u) ? 1 : 0;
    }
    __syncthreads();

    // ── fused finalize: last block to arrive sums all partials ──
    if (s_last) {
        double v = 0.0;
        for (int i = tid; i < (int)gridDim.x; i += BLK)
            v += g_partials[i];
        #pragma unroll
        for (int o = 16; o > 0; o >>= 1)
            v += __shfl_down_sync(0xffffffffu, v, o);
        if (lane == 0) sred[warp] = v;
        __syncthreads();
        if (tid == 0) {
            double t = sred[0] + sred[1] + sred[2] + sred[3];
            out[0] = (float)(t / (double)B);
            g_count = 0;                // reset for next graph replay
        }
    }
}

extern "C" void kernel_launch(void* const* d_in, const int* in_sizes, int n_in,
                              void* d_out, int out_size)
{
    const float* x   = (const float*)d_in[0];   // output       [B, 18]
    const float* lab = (const float*)d_in[1];   // labels_soft  [B, 18]
    const int B = in_sizes[0] / NC;
    const int nchunks = (B + BLK - 1) / BLK;

    int grid = 148 * 6;                 // 6 blocks/SM (36.9 KB smem each)
    if (grid > nchunks) grid = nchunks;
    if (grid > MAX_GRID) grid = MAX_GRID;

    ce_main_kernel<<<grid, BLK>>>(x, lab, (float*)d_out, B, nchunks);
}